// round 8
// baseline (speedup 1.0000x reference)
#include <cuda_runtime.h>

#define B   8
#define D   512
#define T   8192
#define CS  16
#define DH  64
#define NT  16            // t-tiles per batch
#define TCH 32            // chunks per tile
#define TT  512           // columns per tile
#define NTHR 512

// lookback state (reset each launch by reset_kernel)
__device__ float g_agg[B * NT * D];
__device__ int   g_flag[B * NT];

__global__ void reset_kernel() {
    int i = threadIdx.x;
    if (i < B * NT) g_flag[i] = 0;
}

// shared memory layout (floats)
#define CS_OFF 0                       // Cs: 512 x 36  (chunk sums -> pooled -> gate)
#define WS_OFF (512 * 36)              // Ws: 64 x 132  (transposed weight chunk)
#define HS_OFF (WS_OFF + 64 * 132)     // Hs: 64 x 36   (hidden layer)
#define SMEM_FLOATS (HS_OFF + 64 * 36)
#define SMEM_BYTES (SMEM_FLOATS * 4)   // 116,736 B

__global__ void __launch_bounds__(NTHR, 1) fused_kernel(
        const float* __restrict__ x,  const float* __restrict__ w1,
        const float* __restrict__ b1, const float* __restrict__ w2,
        const float* __restrict__ b2, float* __restrict__ out)
{
    extern __shared__ float sm[];
    float* Cs = sm + CS_OFF;
    float* Ws = sm + WS_OFF;
    float* Hs = sm + HS_OFF;

    int tid = threadIdx.x;
    int b = blockIdx.x >> 4;
    int j = blockIdx.x & 15;

    // ---------------- Phase 0: load x tile, 16-chunk sums ----------------
    const float4* xt = reinterpret_cast<const float4*>(x)
                     + ((size_t)(b * D) * T + j * TT) / 4;
    int f4 = tid & 127;       // float4 col within tile
    int r0 = tid >> 7;        // 0..3
    int cc = f4 >> 2;         // chunk 0..31

    #pragma unroll 4
    for (int it = 0; it < 128; it++) {
        int r = it * 4 + r0;
        float4 v = xt[(size_t)r * (T / 4) + f4];
        float s = (v.x + v.y) + (v.z + v.w);
        s += __shfl_xor_sync(0xffffffffu, s, 1);
        s += __shfl_xor_sync(0xffffffffu, s, 2);
        if ((tid & 3) == 0) Cs[r * 36 + cc] = s;
    }
    __syncthreads();

    // ---------------- Phase 1: local scan per row + publish aggregate ----
    {
        float run = 0.f;
        #pragma unroll
        for (int c = 0; c < TCH; c++) {
            run += Cs[tid * 36 + c];
            Cs[tid * 36 + c] = run;
        }
        g_agg[((size_t)b * NT + j) * D + tid] = run;
    }
    __syncthreads();
    if (tid == 0) { __threadfence(); atomicExch(&g_flag[b * NT + j], 1); }

    // ---------------- Phase 2: decoupled lookback ----------------
    float pre = 0.f;
    if (j > 0) {
        if (tid < j) {
            while (atomicAdd(&g_flag[b * NT + tid], 0) == 0) {}
        }
        __threadfence();
        __syncthreads();
        for (int p = 0; p < j; p++)
            pre += g_agg[((size_t)b * NT + p) * D + tid];
    }
    // pooled = (prefix + local inclusive) / count
    #pragma unroll
    for (int c = 0; c < TCH; c++) {
        float denom = (float)(CS * (j * TCH + c + 1));
        Cs[tid * 36 + c] = __fdividef(pre + Cs[tid * 36 + c], denom);
    }
    __syncthreads();

    // ---------------- Phase 3: GEMM1  h[64][32] = W1 @ pooled ----------------
    // thread: c = tid&31, o quad = (tid>>5)*4.  pooled scalar stride-1 LDS,
    // W1 float4 broadcast from transposed smem chunk.
    int c1 = tid & 31;
    int o4 = tid >> 5;        // 0..15
    float h0 = 0.f, h1 = 0.f, h2 = 0.f, h3 = 0.f;

    for (int kc = 0; kc < 8; kc++) {
        #pragma unroll
        for (int i = tid; i < 64 * 64; i += NTHR) {
            int o = i >> 6, kk = i & 63;
            Ws[kk * 132 + o] = w1[o * D + kc * 64 + kk];
        }
        __syncthreads();
        #pragma unroll 8
        for (int kk = 0; kk < 64; kk++) {
            float p = Cs[(kc * 64 + kk) * 36 + c1];
            float4 w = *reinterpret_cast<const float4*>(&Ws[kk * 132 + o4 * 4]);
            h0 = fmaf(w.x, p, h0);
            h1 = fmaf(w.y, p, h1);
            h2 = fmaf(w.z, p, h2);
            h3 = fmaf(w.w, p, h3);
        }
        __syncthreads();
    }
    Hs[(o4 * 4 + 0) * 36 + c1] = fmaxf(h0 + b1[o4 * 4 + 0], 0.f);
    Hs[(o4 * 4 + 1) * 36 + c1] = fmaxf(h1 + b1[o4 * 4 + 1], 0.f);
    Hs[(o4 * 4 + 2) * 36 + c1] = fmaxf(h2 + b1[o4 * 4 + 2], 0.f);
    Hs[(o4 * 4 + 3) * 36 + c1] = fmaxf(h3 + b1[o4 * 4 + 3], 0.f);
    __syncthreads();

    // ---------------- Phase 4: GEMM2  gate[512][32] = sigmoid(W2 @ h + b2) ----
    // 4 o-chunks of 128; thread: 8 o x 1 c; gate overwrites Cs.
    int og = tid >> 5;        // 0..15, o_local = og*8 .. +7
    for (int oc = 0; oc < 4; oc++) {
        #pragma unroll
        for (int i = tid; i < 128 * 64; i += NTHR) {
            int ol = i >> 6, k = i & 63;
            Ws[k * 132 + ol] = w2[(oc * 128 + ol) * DH + k];
        }
        __syncthreads();

        float a[8];
        #pragma unroll
        for (int q = 0; q < 8; q++) a[q] = 0.f;

        #pragma unroll 4
        for (int k = 0; k < 64; k++) {
            float hv = Hs[k * 36 + c1];
            float4 wA = *reinterpret_cast<const float4*>(&Ws[k * 132 + og * 8]);
            float4 wB = *reinterpret_cast<const float4*>(&Ws[k * 132 + og * 8 + 4]);
            a[0] = fmaf(wA.x, hv, a[0]);
            a[1] = fmaf(wA.y, hv, a[1]);
            a[2] = fmaf(wA.z, hv, a[2]);
            a[3] = fmaf(wA.w, hv, a[3]);
            a[4] = fmaf(wB.x, hv, a[4]);
            a[5] = fmaf(wB.y, hv, a[5]);
            a[6] = fmaf(wB.z, hv, a[6]);
            a[7] = fmaf(wB.w, hv, a[7]);
        }
        __syncthreads();   // Ws reads done before next chunk's load

        #pragma unroll
        for (int q = 0; q < 8; q++) {
            int o2 = oc * 128 + og * 8 + q;
            float gv = 1.f / (1.f + __expf(-(a[q] + b2[o2])));
            Cs[o2 * 36 + c1] = gv;     // safe: pooled no longer needed
        }
    }
    __syncthreads();

    // ---------------- Phase 5: out = gate * x (x re-read = CTA-local L2 hit) --
    float4* ot = reinterpret_cast<float4*>(out)
               + ((size_t)(b * D) * T + j * TT) / 4;
    #pragma unroll 4
    for (int it = 0; it < 128; it++) {
        int r = it * 4 + r0;
        size_t idx = (size_t)r * (T / 4) + f4;
        float4 v = xt[idx];
        float gv = Cs[r * 36 + cc];
        float4 o = make_float4(v.x * gv, v.y * gv, v.z * gv, v.w * gv);
        __stcs(&ot[idx], o);
    }
}

// ---------------------------------------------------------------------------
extern "C" void kernel_launch(void* const* d_in, const int* in_sizes, int n_in,
                              void* d_out, int out_size) {
    const float* x  = (const float*)d_in[0];
    const float* w1 = (const float*)d_in[1];
    const float* b1 = (const float*)d_in[2];
    const float* w2 = (const float*)d_in[3];
    const float* b2 = (const float*)d_in[4];
    float* out = (float*)d_out;

    cudaFuncSetAttribute(fused_kernel,
                         cudaFuncAttributeMaxDynamicSharedMemorySize, SMEM_BYTES);
    reset_kernel<<<1, 128>>>();
    fused_kernel<<<B * NT, NTHR, SMEM_BYTES>>>(x, w1, b1, w2, b2, out);
}

// round 9
// speedup vs baseline: 1.4111x; 1.4111x over previous
#include <cuda_runtime.h>

#define B  8
#define D  512
#define T  8192
#define CS 16
#define TC 512   // T / CS
#define DH 64    // D / 8

// Scratch (no cudaMalloc allowed)
__device__ float g_pooled[B * D * TC];          // 8 MiB
__device__ float g_hpart[4][B * DH * TC];       // 1 MiB per split-K slice

// ---------------------------------------------------------------------------
// Kernel 1: per (b,d) row — chunk sums of 16, inclusive scan, divide by count.
// Coalesced block-stride float4 loads (CACHED: keep x resident in L2 for
// gate_scale), lane-group-of-4 reduction, 512-wide block scan. ~23.8 us.
// ---------------------------------------------------------------------------
__global__ void pool_kernel(const float* __restrict__ x) {
    int row = blockIdx.x;                      // b*D + d
    const float4* xr = reinterpret_cast<const float4*>(x) + (size_t)row * (T / 4);
    int j = threadIdx.x;

    __shared__ float csum[TC];
    __shared__ float wsum[16];

    float4 f0 = xr[j];
    float4 f1 = xr[j + 512];
    float4 f2 = xr[j + 1024];
    float4 f3 = xr[j + 1536];

    float s0 = (f0.x + f0.y) + (f0.z + f0.w);
    float s1 = (f1.x + f1.y) + (f1.z + f1.w);
    float s2 = (f2.x + f2.y) + (f2.z + f2.w);
    float s3 = (f3.x + f3.y) + (f3.z + f3.w);

    s0 += __shfl_xor_sync(0xffffffffu, s0, 1);
    s0 += __shfl_xor_sync(0xffffffffu, s0, 2);
    s1 += __shfl_xor_sync(0xffffffffu, s1, 1);
    s1 += __shfl_xor_sync(0xffffffffu, s1, 2);
    s2 += __shfl_xor_sync(0xffffffffu, s2, 1);
    s2 += __shfl_xor_sync(0xffffffffu, s2, 2);
    s3 += __shfl_xor_sync(0xffffffffu, s3, 1);
    s3 += __shfl_xor_sync(0xffffffffu, s3, 2);

    if ((j & 3) == 0) {
        int c = j >> 2;
        csum[c +   0] = s0;
        csum[c + 128] = s1;
        csum[c + 256] = s2;
        csum[c + 384] = s3;
    }
    __syncthreads();

    int lane = j & 31, warp = j >> 5;
    float v = csum[j];
    #pragma unroll
    for (int off = 1; off < 32; off <<= 1) {
        float n = __shfl_up_sync(0xffffffffu, v, off);
        if (lane >= off) v += n;
    }
    if (lane == 31) wsum[warp] = v;
    __syncthreads();
    if (warp == 0) {
        float w = (lane < 16) ? wsum[lane] : 0.f;
        #pragma unroll
        for (int off = 1; off < 16; off <<= 1) {
            float n = __shfl_up_sync(0xffffffffu, w, off);
            if (lane >= off) w += n;
        }
        if (lane < 16) wsum[lane] = w;
    }
    __syncthreads();

    float prefix = (warp > 0) ? wsum[warp - 1] : 0.f;
    float total  = v + prefix;
    g_pooled[(size_t)row * TC + j] = total / (float)(CS * (j + 1));
}

// ---------------------------------------------------------------------------
// Kernel 2a: GEMM1 split-K partials (occupancy-tiled). ~9 us.
// grid (8 t-tiles, 4 k-slices, B) = 256 CTAs, 256 threads, smem ~33 KiB.
// ---------------------------------------------------------------------------
__global__ void __launch_bounds__(256) gemm1_kernel(const float* __restrict__ w1) {
    __shared__ __align__(16) float Ps[64 * 64];      // [d][t] 16 KiB
    __shared__ __align__(16) float Ws[64 * 65 + 4];  // [o][d] padded

    int tid = threadIdx.x;
    int t0 = blockIdx.x * 64;
    int k0 = blockIdx.y * 128;
    int b  = blockIdx.z;
    int tq = tid & 15;          // t quad -> t = tq*4..tq*4+3
    int og = tid >> 4;          // 0..15  -> o = og*4..og*4+3

    float acc[4][4];
    #pragma unroll
    for (int o = 0; o < 4; o++)
        #pragma unroll
        for (int q = 0; q < 4; q++) acc[o][q] = 0.f;

    for (int c = 0; c < 2; c++) {
        int kc = k0 + c * 64;
        #pragma unroll
        for (int i = tid; i < 64 * 16; i += 256) {
            int d = i >> 4, t4 = i & 15;
            *reinterpret_cast<float4*>(&Ps[d * 64 + t4 * 4]) =
                *reinterpret_cast<const float4*>(
                    &g_pooled[((size_t)(b * D) + kc + d) * TC + t0 + t4 * 4]);
        }
        #pragma unroll
        for (int i = tid; i < 64 * 64; i += 256) {
            int o = i >> 6, d = i & 63;
            Ws[o * 65 + d] = w1[o * D + kc + d];
        }
        __syncthreads();

        #pragma unroll 8
        for (int dd = 0; dd < 64; dd++) {
            float4 p = *reinterpret_cast<const float4*>(&Ps[dd * 64 + tq * 4]);
            #pragma unroll
            for (int o = 0; o < 4; o++) {
                float w = Ws[(og * 4 + o) * 65 + dd];
                acc[o][0] = fmaf(w, p.x, acc[o][0]);
                acc[o][1] = fmaf(w, p.y, acc[o][1]);
                acc[o][2] = fmaf(w, p.z, acc[o][2]);
                acc[o][3] = fmaf(w, p.w, acc[o][3]);
            }
        }
        __syncthreads();
    }

    float* hp = g_hpart[blockIdx.y];
    #pragma unroll
    for (int o = 0; o < 4; o++) {
        float4 v = make_float4(acc[o][0], acc[o][1], acc[o][2], acc[o][3]);
        *reinterpret_cast<float4*>(
            &hp[((size_t)(b * DH) + og * 4 + o) * TC + t0 + tq * 4]) = v;
    }
}

// ---------------------------------------------------------------------------
// Kernel 2b (FUSED): gemm2 + sigmoid gate + out = gate * x.
// Finer tiles for cross-CTA overlap: t-tile 32 chunks (512 cols), o-tile 64.
// grid (16, 8, 8) = 1024 CTAs (~7 waves), 256 threads, smem ~25 KiB.
// y and z REVERSED so first CTAs read the x lines pool cached most recently.
// x reads cached; out writes streaming (__stcs).
// ---------------------------------------------------------------------------
__global__ void __launch_bounds__(256) gate_scale_kernel(
        const float* __restrict__ w2,
        const float* __restrict__ b1,
        const float* __restrict__ b2,
        const float* __restrict__ x,
        float* __restrict__ out) {
    __shared__ __align__(16) float Hs[64 * 32];      // [k][t] then gate [o][t]
    __shared__ __align__(16) float Ws[64 * 65 + 4];  // [o][k] padded

    int tid = threadIdx.x;
    int t0 = blockIdx.x * 32;                 // pooled-chunk tile start
    int o0 = (7 - blockIdx.y) * 64;           // reversed d-tile
    int b  = (B - 1) - blockIdx.z;            // reversed batch
    int tq = tid & 7;                         // t quad: t = tq*4..+3
    int og = tid >> 3;                        // 0..31 -> o = og*2, og*2+1

    // ---- Phase A1: H = relu(sum hpart + b1), W2 ----
    #pragma unroll
    for (int i = tid; i < 64 * 8; i += 256) {
        int k = i >> 3, t4 = i & 7;
        size_t idx = ((size_t)(b * DH) + k) * TC + t0 + t4 * 4;
        float4 a0 = *reinterpret_cast<const float4*>(&g_hpart[0][idx]);
        float4 a1 = *reinterpret_cast<const float4*>(&g_hpart[1][idx]);
        float4 a2 = *reinterpret_cast<const float4*>(&g_hpart[2][idx]);
        float4 a3 = *reinterpret_cast<const float4*>(&g_hpart[3][idx]);
        float bb = b1[k];
        float4 hv;
        hv.x = fmaxf(a0.x + a1.x + a2.x + a3.x + bb, 0.f);
        hv.y = fmaxf(a0.y + a1.y + a2.y + a3.y + bb, 0.f);
        hv.z = fmaxf(a0.z + a1.z + a2.z + a3.z + bb, 0.f);
        hv.w = fmaxf(a0.w + a1.w + a2.w + a3.w + bb, 0.f);
        *reinterpret_cast<float4*>(&Hs[k * 32 + t4 * 4]) = hv;
    }
    #pragma unroll
    for (int i = tid; i < 64 * 64; i += 256) {
        int o = i >> 6, k = i & 63;
        Ws[o * 65 + k] = w2[(o0 + o) * DH + k];
    }
    __syncthreads();

    // ---- Phase A2: GEMM 64o x 32t, K=64; thread = 2o x 4t ----
    float acc[2][4];
    acc[0][0] = acc[0][1] = acc[0][2] = acc[0][3] = 0.f;
    acc[1][0] = acc[1][1] = acc[1][2] = acc[1][3] = 0.f;

    #pragma unroll 8
    for (int k = 0; k < 64; k++) {
        float4 h = *reinterpret_cast<const float4*>(&Hs[k * 32 + tq * 4]);
        float w0 = Ws[(og * 2 + 0) * 65 + k];
        float w1v = Ws[(og * 2 + 1) * 65 + k];
        acc[0][0] = fmaf(w0, h.x, acc[0][0]);
        acc[0][1] = fmaf(w0, h.y, acc[0][1]);
        acc[0][2] = fmaf(w0, h.z, acc[0][2]);
        acc[0][3] = fmaf(w0, h.w, acc[0][3]);
        acc[1][0] = fmaf(w1v, h.x, acc[1][0]);
        acc[1][1] = fmaf(w1v, h.y, acc[1][1]);
        acc[1][2] = fmaf(w1v, h.z, acc[1][2]);
        acc[1][3] = fmaf(w1v, h.w, acc[1][3]);
    }
    __syncthreads();   // Hs reads done; reuse as gate

    // ---- Phase A3: sigmoid -> gate tile [o_local][32 t] ----
    #pragma unroll
    for (int o = 0; o < 2; o++) {
        float bb = b2[o0 + og * 2 + o];
        float4 g;
        g.x = 1.f / (1.f + __expf(-(acc[o][0] + bb)));
        g.y = 1.f / (1.f + __expf(-(acc[o][1] + bb)));
        g.z = 1.f / (1.f + __expf(-(acc[o][2] + bb)));
        g.w = 1.f / (1.f + __expf(-(acc[o][3] + bb)));
        *reinterpret_cast<float4*>(&Hs[(og * 2 + o) * 32 + tq * 4]) = g;
    }
    __syncthreads();

    // ---- Phase B: out = gate * x over [64 d-rows][512 cols] ----
    // Warp w: rows w*8..w*8+7; each row = 128 float4, 4 per lane.
    int warp = tid >> 5, lane = tid & 31;
    int c0 = t0 * CS;

    #pragma unroll
    for (int r = 0; r < 8; r++) {
        int o_local = warp * 8 + r;
        size_t rowbase = ((size_t)(b * D) + o0 + o_local) * T + c0;
        const float4* xr = reinterpret_cast<const float4*>(x + rowbase);
        float4*       orp = reinterpret_cast<float4*>(out + rowbase);

        float4 xv[4];
        #pragma unroll
        for (int i = 0; i < 4; i++)
            xv[i] = xr[i * 32 + lane];        // cached — expect L2 hit

        float gv[4];
        #pragma unroll
        for (int i = 0; i < 4; i++)
            gv[i] = Hs[o_local * 32 + ((i * 32 + lane) >> 2)];

        #pragma unroll
        for (int i = 0; i < 4; i++) {
            float4 ov = make_float4(xv[i].x * gv[i], xv[i].y * gv[i],
                                    xv[i].z * gv[i], xv[i].w * gv[i]);
            __stcs(&orp[i * 32 + lane], ov);
        }
    }
}

// ---------------------------------------------------------------------------
extern "C" void kernel_launch(void* const* d_in, const int* in_sizes, int n_in,
                              void* d_out, int out_size) {
    const float* x  = (const float*)d_in[0];
    const float* w1 = (const float*)d_in[1];
    const float* b1 = (const float*)d_in[2];
    const float* w2 = (const float*)d_in[3];
    const float* b2 = (const float*)d_in[4];
    float* out = (float*)d_out;

    pool_kernel<<<B * D, 512>>>(x);
    gemm1_kernel<<<dim3(8, 4, B), 256>>>(w1);
    gate_scale_kernel<<<dim3(16, 8, B), 256>>>(w2, b1, b2, x, out);
}